// round 9
// baseline (speedup 1.0000x reference)
#include <cuda_runtime.h>
#include <cstdint>

// Problem constants
#define NB    4
#define TSEQ  4096
#define CDIM  1024
#define HDIM  64
#define MROWS (NB * TSEQ)   // 16384

typedef unsigned long long u64;

// ---- packed f32x2 helpers (sm_103a FFMA2 path) ----
__device__ __forceinline__ u64 pk2(float lo, float hi) {
    u64 d;
    asm("mov.b64 %0, {%1, %2};" : "=l"(d) : "f"(lo), "f"(hi));
    return d;
}
__device__ __forceinline__ void upk2(float& lo, float& hi, u64 v) {
    asm("mov.b64 {%0, %1}, %2;" : "=f"(lo), "=f"(hi) : "l"(v));
}
__device__ __forceinline__ void fma2(u64& d, u64 a, u64 b) {
    asm("fma.rn.f32x2 %0, %1, %2, %0;" : "+l"(d) : "l"(a), "l"(b));
}
__device__ __forceinline__ void mul2(u64& d, u64 a) {
    asm("mul.rn.f32x2 %0, %0, %1;" : "+l"(d) : "l"(a));
}

// Scratch for projected q, k, v  (12 MB total) — __device__ globals per alloc rules
__device__ float g_q[MROWS * HDIM];
__device__ float g_k[MROWS * HDIM];
__device__ float g_v[MROWS * HDIM];

// ---------------------------------------------------------------------------
// Projection: out[m][h] = sum_c x[m][c] * W[h][c]
// BM=128, BN=64, BK=32, 256 threads, 8x4 microtile, f32x2 packed over c-pairs.
// (unchanged this round — single-variable experiment on attention)
// ---------------------------------------------------------------------------
#define PJ_STR 36   // 32 + 4 pad

__global__ __launch_bounds__(256) void proj_kernel(
    const float* __restrict__ x,
    const float* __restrict__ Wq,
    const float* __restrict__ Wk,
    const float* __restrict__ Wv)
{
    __shared__ float As[128 * PJ_STR];  // x tile [m][c]
    __shared__ float Bs[64 * PJ_STR];   // W tile [n][c]

    const int wsel = blockIdx.y;
    const float* __restrict__ W = (wsel == 0) ? Wq : ((wsel == 1) ? Wk : Wv);
    float* __restrict__ dst     = (wsel == 0) ? g_q : ((wsel == 1) ? g_k : g_v);

    const int m0 = blockIdx.x * 128;
    const int t  = threadIdx.x;
    const int tx = t & 15;
    const int ty = t >> 4;
    const int lrow = t >> 3;         // 0..31
    const int lc   = (t & 7) * 4;    // 0..28

    u64 acc[8][4] = {};              // packed (even c, odd c) partials

    for (int kb = 0; kb < CDIM; kb += 32) {
        #pragma unroll
        for (int p = 0; p < 4; p++) {     // As: 128 rows
            const int row = lrow + p * 32;
            *(float4*)(As + row * PJ_STR + lc) =
                *(const float4*)(x + (m0 + row) * CDIM + kb + lc);
        }
        #pragma unroll
        for (int p = 0; p < 2; p++) {     // Bs: 64 rows
            const int row = lrow + p * 32;
            *(float4*)(Bs + row * PJ_STR + lc) =
                *(const float4*)(W + row * CDIM + kb + lc);
        }
        __syncthreads();

        #pragma unroll
        for (int kk = 0; kk < 32; kk += 4) {
            ulonglong2 a2[8], b2[4];
            #pragma unroll
            for (int ii = 0; ii < 8; ii++)
                a2[ii] = *(const ulonglong2*)(As + (ty + 16 * ii) * PJ_STR + kk);
            #pragma unroll
            for (int jj = 0; jj < 4; jj++)
                b2[jj] = *(const ulonglong2*)(Bs + (tx + 16 * jj) * PJ_STR + kk);
            #pragma unroll
            for (int ii = 0; ii < 8; ii++)
                #pragma unroll
                for (int jj = 0; jj < 4; jj++) {
                    fma2(acc[ii][jj], a2[ii].x, b2[jj].x);
                    fma2(acc[ii][jj], a2[ii].y, b2[jj].y);
                }
        }
        __syncthreads();
    }

    #pragma unroll
    for (int ii = 0; ii < 8; ii++)
        #pragma unroll
        for (int jj = 0; jj < 4; jj++) {
            float lo, hi;
            upk2(lo, hi, acc[ii][jj]);
            dst[(m0 + ty + 16 * ii) * HDIM + (tx + 16 * jj)] = lo + hi;
        }
}

// ---------------------------------------------------------------------------
// Flash attention (fp32 via f32x2, causal). grid = (32, 4), 512 THREADS:
// each CTA does the complementary q-tile pair (63-bx, bx) -> uniform 65
// iterations; 16 warps/SM (4/SMSP) hide LDS/SHFL/MUFU latency that capped
// the 256-thread version (issue was 37%).
// Thread map: tx = t&31 -> 2 output cols (one f32x2 pair) / 2 S-col groups;
//             ty = t>>5 -> 4 rows (ty + 16*ii). Per-warp ty is constant, so
// Q operands and PV P-reads are full-warp broadcasts; row reductions are
// 32-lane xor-shuffle trees.
// K/V double-buffered via register prefetch; 2 barriers/iter.
// Smem padded to >113KB to force exactly 1 CTA/SM (2 CTAs would unbalance).
// ---------------------------------------------------------------------------
#define AT_STR  68
#define KV_BUF  (64 * AT_STR)
#define SM_QS   0
#define SM_KS   (64 * AT_STR)
#define SM_VS   (3 * 64 * AT_STR)
#define SM_ST   (5 * 64 * AT_STR)
#define SM_TOTF (6 * 64 * AT_STR)                 // 26112 floats
#define ATTN_SMEM_BYTES (SM_TOTF * 4 + 16384)     // 120832 B -> 1 CTA/SM

__global__ __launch_bounds__(512) void attn_kernel(float* __restrict__ out)
{
    extern __shared__ float sm[];
    float* Qs = sm + SM_QS;
    float* Ks = sm + SM_KS;   // Ks + cur*KV_BUF
    float* Vs = sm + SM_VS;
    float* St = sm + SM_ST;

    const int t  = threadIdx.x;
    const int tx = t & 31;                // col-pair group / S col group
    const int ty = t >> 5;                // 0..15 : row group (warp-uniform)
    const int bx = blockIdx.x;            // 0..31
    const int b  = blockIdx.y;
    const float NEGBIG = -1e30f;
    const float scale  = 0.125f;          // 64^-0.5

    // cooperative tile-load map: 2 float4 per thread (64x64 tile, 512 thr)
    const int lrow0 = t >> 4;             // f>>4 for f = t, t+512
    const int lcol  = (t & 15) * 4;

    const float* __restrict__ kbase = g_k + b * TSEQ * HDIM;
    const float* __restrict__ vbase = g_v + b * TSEQ * HDIM;

    #pragma unroll 1
    for (int half = 0; half < 2; half++) {
        const int qb = (half == 0) ? (63 - bx) : bx;   // heavy tile first

        // ---- load Q tile (pre-scaled) + prologue K/V(0) into buf 0 ----
        {
            const float* __restrict__ qsrc = g_q + (b * TSEQ + qb * 64) * HDIM;
            #pragma unroll
            for (int p = 0; p < 2; p++) {
                const int row = lrow0 + p * 32;
                float4 q4 = *(const float4*)(qsrc + row * HDIM + lcol);
                q4.x *= scale; q4.y *= scale; q4.z *= scale; q4.w *= scale;
                *(float4*)(Qs + row * AT_STR + lcol) = q4;
                *(float4*)(Ks + row * AT_STR + lcol) =
                    *(const float4*)(kbase + row * HDIM + lcol);
                *(float4*)(Vs + row * AT_STR + lcol) =
                    *(const float4*)(vbase + row * HDIM + lcol);
            }
        }

        float m_i[4], l_i[4];
        #pragma unroll
        for (int ii = 0; ii < 4; ii++) { m_i[ii] = NEGBIG; l_i[ii] = 0.0f; }
        u64 o[4] = {};                    // packed output col pair per row

        __syncthreads();                               // prologue barrier

        for (int jt = 0; jt <= qb; jt++) {
            const int cur = jt & 1;
            float* __restrict__ Kc = Ks + cur * KV_BUF;
            float* __restrict__ Vc = Vs + cur * KV_BUF;

            // ---- prefetch next K/V tile into registers ----
            float4 kpf[2], vpf[2];
            const bool pf = (jt < qb);
            if (pf) {
                const float* __restrict__ ksrc = kbase + (jt + 1) * 64 * HDIM;
                const float* __restrict__ vsrc = vbase + (jt + 1) * 64 * HDIM;
                #pragma unroll
                for (int p = 0; p < 2; p++) {
                    const int row = lrow0 + p * 32;
                    kpf[p] = *(const float4*)(ksrc + row * HDIM + lcol);
                    vpf[p] = *(const float4*)(vsrc + row * HDIM + lcol);
                }
            }

            // ---- S = (Q*scale) @ K^T : packed over kk pairs ----
            // rows ty+16*ii (Q loads warp-broadcast), cols tx+32*jj
            u64 sp[4][2] = {};
            #pragma unroll
            for (int kk = 0; kk < 64; kk += 4) {
                ulonglong2 a2[4], b2[2];
                #pragma unroll
                for (int ii = 0; ii < 4; ii++)
                    a2[ii] = *(const ulonglong2*)(Qs + (ty + 16 * ii) * AT_STR + kk);
                #pragma unroll
                for (int jj = 0; jj < 2; jj++)
                    b2[jj] = *(const ulonglong2*)(Kc + (tx + 32 * jj) * AT_STR + kk);
                #pragma unroll
                for (int ii = 0; ii < 4; ii++)
                    #pragma unroll
                    for (int jj = 0; jj < 2; jj++) {
                        fma2(sp[ii][jj], a2[ii].x, b2[jj].x);
                        fma2(sp[ii][jj], a2[ii].y, b2[jj].y);
                    }
            }
            // fold packed partials
            float s[4][2];
            #pragma unroll
            for (int ii = 0; ii < 4; ii++)
                #pragma unroll
                for (int jj = 0; jj < 2; jj++) {
                    float lo, hi;
                    upk2(lo, hi, sp[ii][jj]);
                    s[ii][jj] = lo + hi;
                }

            // causal mask on the diagonal tile
            if (jt == qb) {
                #pragma unroll
                for (int ii = 0; ii < 4; ii++)
                    #pragma unroll
                    for (int jj = 0; jj < 2; jj++)
                        if ((tx + 32 * jj) > (ty + 16 * ii)) s[ii][jj] = NEGBIG;
            }

            // ---- online softmax (register-resident, 32-lane shuffle trees) ----
            #pragma unroll
            for (int ii = 0; ii < 4; ii++) {
                float tm = fmaxf(s[ii][0], s[ii][1]);
                #pragma unroll
                for (int w = 1; w < 32; w <<= 1)
                    tm = fmaxf(tm, __shfl_xor_sync(0xffffffffu, tm, w));
                const float mnew = fmaxf(m_i[ii], tm);
                const float alpha = __expf(m_i[ii] - mnew);
                m_i[ii] = mnew;

                float p0 = __expf(s[ii][0] - mnew);
                float p1 = __expf(s[ii][1] - mnew);
                float rs = p0 + p1;
                #pragma unroll
                for (int w = 1; w < 32; w <<= 1)
                    rs += __shfl_xor_sync(0xffffffffu, rs, w);
                l_i[ii] = l_i[ii] * alpha + rs;

                mul2(o[ii], pk2(alpha, alpha));

                const int pc = ty * 4 + ii;           // P[row] slot 0..63
                St[(tx +  0) * AT_STR + pc] = p0;
                St[(tx + 32) * AT_STR + pc] = p1;
            }
            __syncthreads();                           // barrier A: St ready

            // ---- O += P @ V : P f4 warp-broadcast, V f32x2 native pair ----
            #pragma unroll 8
            for (int j = 0; j < 64; j++) {
                const float4 pv = *(const float4*)(St + j * AT_STR + ty * 4);
                const u64 vv = *(const u64*)(Vc + j * AT_STR + tx * 2);
                fma2(o[0], pk2(pv.x, pv.x), vv);
                fma2(o[1], pk2(pv.y, pv.y), vv);
                fma2(o[2], pk2(pv.z, pv.z), vv);
                fma2(o[3], pk2(pv.w, pv.w), vv);
            }

            // ---- stage prefetched K/V into the alternate buffer ----
            if (pf) {
                float* __restrict__ Kn = Ks + (1 - cur) * KV_BUF;
                float* __restrict__ Vn = Vs + (1 - cur) * KV_BUF;
                #pragma unroll
                for (int p = 0; p < 2; p++) {
                    const int row = lrow0 + p * 32;
                    *(float4*)(Kn + row * AT_STR + lcol) = kpf[p];
                    *(float4*)(Vn + row * AT_STR + lcol) = vpf[p];
                }
            }
            __syncthreads();                           // barrier B: bufs/St safe
        }

        // ---- epilogue: out = O / l ----
        #pragma unroll
        for (int ii = 0; ii < 4; ii++) {
            const int i     = ty + 16 * ii;
            const float inv = 1.0f / l_i[ii];
            float c0, c1;
            upk2(c0, c1, o[ii]);
            float2 ov;
            ov.x = c0 * inv; ov.y = c1 * inv;
            *(float2*)(out + (b * TSEQ + qb * 64 + i) * HDIM + tx * 2) = ov;
        }
    }
}

// ---------------------------------------------------------------------------
// kernel_launch — inputs (metadata order): x, mask(int32, unused), Wk, Wq, Wv
// ---------------------------------------------------------------------------
extern "C" void kernel_launch(void* const* d_in, const int* in_sizes, int n_in,
                              void* d_out, int out_size)
{
    const float* x  = (const float*)d_in[0];
    // d_in[1] = mask (int32) — causality is known; not read.
    const float* Wk = (const float*)d_in[2];
    const float* Wq = (const float*)d_in[3];
    const float* Wv = (const float*)d_in[4];
    float* out = (float*)d_out;

    // Host-side attribute set; not a stream op, safe under graph capture.
    cudaFuncSetAttribute(attn_kernel,
                         cudaFuncAttributeMaxDynamicSharedMemorySize,
                         ATTN_SMEM_BYTES);

    dim3 pgrid(MROWS / 128, 3);
    proj_kernel<<<pgrid, 256>>>(x, Wq, Wk, Wv);

    dim3 agrid(32, NB);   // paired q-tiles: uniform 65 iterations per CTA
    attn_kernel<<<agrid, 512, ATTN_SMEM_BYTES>>>(out);
}

// round 11
// speedup vs baseline: 1.3904x; 1.3904x over previous
#include <cuda_runtime.h>
#include <cuda_bf16.h>
#include <cstdint>

// Problem constants
#define NB    4
#define TSEQ  4096
#define CDIM  1024
#define HDIM  64
#define MROWS (NB * TSEQ)   // 16384

typedef unsigned long long u64;

// ---- packed f32x2 helpers (sm_103a FFMA2 path) ----
__device__ __forceinline__ u64 pk2(float lo, float hi) {
    u64 d;
    asm("mov.b64 %0, {%1, %2};" : "=l"(d) : "f"(lo), "f"(hi));
    return d;
}
__device__ __forceinline__ void upk2(float& lo, float& hi, u64 v) {
    asm("mov.b64 {%0, %1}, %2;" : "=f"(lo), "=f"(hi) : "l"(v));
}
__device__ __forceinline__ void fma2(u64& d, u64 a, u64 b) {
    asm("fma.rn.f32x2 %0, %1, %2, %0;" : "+l"(d) : "l"(a), "l"(b));
}
__device__ __forceinline__ void mul2(u64& d, u64 a) {
    asm("mul.rn.f32x2 %0, %0, %1;" : "+l"(d) : "l"(a));
}

__device__ __forceinline__ uint32_t smem_to_u32(const void* p) {
    uint32_t a;
    asm("{ .reg .u64 t; cvta.to.shared.u64 t, %1; cvt.u32.u64 %0, t; }"
        : "=r"(a) : "l"(p));
    return a;
}
#define SMEM_SWIZZLE_128B(off) ((off) ^ (((off) >> 3) & 0x70))

// ---- legacy tensor-core path (compute_103-legal): ldmatrix + mma.sync ----
__device__ __forceinline__ void ldsm_x4(uint32_t& r0, uint32_t& r1,
                                        uint32_t& r2, uint32_t& r3,
                                        uint32_t addr) {
    asm volatile("ldmatrix.sync.aligned.m8n8.x4.shared.b16 {%0,%1,%2,%3}, [%4];"
                 : "=r"(r0), "=r"(r1), "=r"(r2), "=r"(r3) : "r"(addr));
}
__device__ __forceinline__ void mma_bf16(float* d, const uint32_t* a,
                                         const uint32_t* b) {
    asm volatile(
        "mma.sync.aligned.m16n8k16.row.col.f32.bf16.bf16.f32 "
        "{%0,%1,%2,%3}, {%4,%5,%6,%7}, {%8,%9}, {%0,%1,%2,%3};"
        : "+f"(d[0]), "+f"(d[1]), "+f"(d[2]), "+f"(d[3])
        : "r"(a[0]), "r"(a[1]), "r"(a[2]), "r"(a[3]), "r"(b[0]), "r"(b[1]));
}

// Scratch (device globals per alloc rules)
__device__ float g_q[MROWS * HDIM];
__device__ float g_k[MROWS * HDIM];
__device__ float g_v[MROWS * HDIM];
__device__ __nv_bfloat16 g_xh[MROWS * CDIM];   // 32 MB
__device__ __nv_bfloat16 g_xl[MROWS * CDIM];   // 32 MB
__device__ __nv_bfloat16 g_wh[3 * HDIM * CDIM];
__device__ __nv_bfloat16 g_wl[3 * HDIM * CDIM];

// ---------------------------------------------------------------------------
// fp32 -> bf16 two-term split: v = hi + lo (+ O(2^-17 v))
// ---------------------------------------------------------------------------
__global__ __launch_bounds__(256) void cvt_split_kernel(
    const float* __restrict__ src,
    __nv_bfloat16* __restrict__ dhi,
    __nv_bfloat16* __restrict__ dlo, int n)
{
    const int i = (blockIdx.x * 256 + threadIdx.x) * 4;
    if (i >= n) return;
    const float4 v = *(const float4*)(src + i);
    const float vv[4] = {v.x, v.y, v.z, v.w};
    __nv_bfloat16 h[4], l[4];
    #pragma unroll
    for (int k = 0; k < 4; k++) {
        h[k] = __float2bfloat16(vv[k]);
        l[k] = __float2bfloat16(vv[k] - __bfloat162float(h[k]));
    }
    *(uint2*)(dhi + i) = *(uint2*)h;
    *(uint2*)(dlo + i) = *(uint2*)l;
}

// ---------------------------------------------------------------------------
// Projection via mma.sync bf16-split: out[m][h] = sum_c x[m][c] W[h][c]
// BM=128, BN=64(=HDIM), BK=64 bf16 (128B SW128 rows), 256 thr = 8 warps (4Mx2N).
// Per warp: 32 rows x 32 cols = 2 m16-tiles x 4 n8-tiles; 3 split products.
// grid = (MROWS/128, 3); blockIdx.y selects W / destination.
// ---------------------------------------------------------------------------
#define PM_AH   0
#define PM_AL   16384
#define PM_BH   32768
#define PM_BL   40960
#define PM_SMEM 49152

__global__ __launch_bounds__(256) void proj_mma_kernel()
{
    extern __shared__ char smem[];
    const uint32_t sb = smem_to_u32(smem);
    const int t   = threadIdx.x;
    const int wid = t >> 5;
    const int lid = t & 31;
    const int m0  = blockIdx.x * 128;
    const int ws  = blockIdx.y;

    const __nv_bfloat16* __restrict__ Wh = g_wh + ws * HDIM * CDIM;
    const __nv_bfloat16* __restrict__ Wl = g_wl + ws * HDIM * CDIM;
    float* __restrict__ dst = (ws == 0) ? g_q : ((ws == 1) ? g_k : g_v);

    const int warp_m = (wid >> 1) * 32;   // 0,32,64,96
    const int warp_n = (wid & 1) * 32;    // 0,32

    // ldmatrix lane-address components
    const int g  = lid >> 3;              // matrix group 0..3
    const int r  = lid & 7;               // row within 8x8

    float d[2][4][4] = {};                // [m-tile][n-tile][frag]

    for (int kb = 0; kb < CDIM; kb += 64) {
        // ---- stage A (128x64 x2 terms) and B (64x64 x2 terms), SW128 ----
        #pragma unroll
        for (int p = 0; p < 4; p++) {
            const int u   = t + p * 256;
            const int row = u >> 3;
            const int cu  = u & 7;
            const uint32_t so = SMEM_SWIZZLE_128B((uint32_t)(row * 128 + cu * 16));
            const long gi = (long)(m0 + row) * CDIM + kb + cu * 8;
            *(uint4*)(smem + PM_AH + so) = *(const uint4*)(g_xh + gi);
            *(uint4*)(smem + PM_AL + so) = *(const uint4*)(g_xl + gi);
        }
        #pragma unroll
        for (int p = 0; p < 2; p++) {
            const int u   = t + p * 256;
            const int row = u >> 3;
            const int cu  = u & 7;
            const uint32_t so = SMEM_SWIZZLE_128B((uint32_t)(row * 128 + cu * 16));
            const int gi = row * CDIM + kb + cu * 8;
            *(uint4*)(smem + PM_BH + so) = *(const uint4*)(Wh + gi);
            *(uint4*)(smem + PM_BL + so) = *(const uint4*)(Wl + gi);
        }
        __syncthreads();

        #pragma unroll
        for (int ks = 0; ks < 4; ks++) {
            const int k0 = ks * 16;

            // A fragments: groups (g&1)->row half, (g>>1)->k half
            uint32_t ah[2][4], al[2][4];
            #pragma unroll
            for (int mt = 0; mt < 2; mt++) {
                const int arow = warp_m + mt * 16 + r + (g & 1) * 8;
                const int acol = k0 + (g >> 1) * 8;
                const uint32_t so =
                    SMEM_SWIZZLE_128B((uint32_t)(arow * 128 + acol * 2));
                ldsm_x4(ah[mt][0], ah[mt][1], ah[mt][2], ah[mt][3],
                        sb + PM_AH + so);
                ldsm_x4(al[mt][0], al[mt][1], al[mt][2], al[mt][3],
                        sb + PM_AL + so);
            }
            // B fragments: x4 covers 2 n8-tiles x 2 k-halves
            // groups: (g>>1)->n half (n0 / n0+8), (g&1)->k half
            uint32_t bh[4][2], bl[4][2];
            #pragma unroll
            for (int np = 0; np < 2; np++) {
                const int brow = warp_n + np * 16 + r + (g >> 1) * 8;
                const int bcol = k0 + (g & 1) * 8;
                const uint32_t so =
                    SMEM_SWIZZLE_128B((uint32_t)(brow * 128 + bcol * 2));
                uint32_t r0, r1, r2, r3;
                ldsm_x4(r0, r1, r2, r3, sb + PM_BH + so);
                bh[np * 2 + 0][0] = r0; bh[np * 2 + 0][1] = r1;
                bh[np * 2 + 1][0] = r2; bh[np * 2 + 1][1] = r3;
                ldsm_x4(r0, r1, r2, r3, sb + PM_BL + so);
                bl[np * 2 + 0][0] = r0; bl[np * 2 + 0][1] = r1;
                bl[np * 2 + 1][0] = r2; bl[np * 2 + 1][1] = r3;
            }

            #pragma unroll
            for (int mt = 0; mt < 2; mt++)
                #pragma unroll
                for (int nt = 0; nt < 4; nt++) {
                    mma_bf16(d[mt][nt], ah[mt], bh[nt]);   // xh*wh
                    mma_bf16(d[mt][nt], ah[mt], bl[nt]);   // xh*wl
                    mma_bf16(d[mt][nt], al[mt], bh[nt]);   // xl*wh
                }
        }
        __syncthreads();
    }

    // ---- epilogue: fragment -> dst (fp32). lane holds rows q, q+8; cols 2c,2c+1
    const int qrow = lid >> 2;
    const int qcol = (lid & 3) * 2;
    #pragma unroll
    for (int mt = 0; mt < 2; mt++)
        #pragma unroll
        for (int nt = 0; nt < 4; nt++) {
            const int row0 = m0 + warp_m + mt * 16 + qrow;
            const int col  = warp_n + nt * 8 + qcol;
            *(float2*)(dst + (long)row0 * HDIM + col) =
                make_float2(d[mt][nt][0], d[mt][nt][1]);
            *(float2*)(dst + (long)(row0 + 8) * HDIM + col) =
                make_float2(d[mt][nt][2], d[mt][nt][3]);
        }
}

// ---------------------------------------------------------------------------
// Flash attention — UNCHANGED from R8 (best measured: 289.6us).
// ---------------------------------------------------------------------------
#define AT_STR  68
#define KV_BUF  (64 * AT_STR)
#define SM_QS   0
#define SM_KS   (64 * AT_STR)
#define SM_VS   (3 * 64 * AT_STR)
#define SM_ST   (5 * 64 * AT_STR)
#define SM_TOTF (6 * 64 * AT_STR)           // 26112 floats
#define ATTN_SMEM_BYTES (SM_TOTF * 4)       // 104448 bytes

__global__ __launch_bounds__(256) void attn_kernel(float* __restrict__ out)
{
    extern __shared__ float sm[];
    float* Qs = sm + SM_QS;
    float* Ks = sm + SM_KS;
    float* Vs = sm + SM_VS;
    float* St = sm + SM_ST;

    const int t  = threadIdx.x;
    const int tx = t & 15;
    const int ty = t >> 4;
    const int bx = blockIdx.x;
    const int b  = blockIdx.y;
    const float NEGBIG = -1e30f;
    const float scale  = 0.125f;

    const int lrow0 = t >> 4;
    const int lcol  = (t & 15) * 4;

    const float* __restrict__ kbase = g_k + b * TSEQ * HDIM;
    const float* __restrict__ vbase = g_v + b * TSEQ * HDIM;

    #pragma unroll 1
    for (int half = 0; half < 2; half++) {
        const int qb = (half == 0) ? (63 - bx) : bx;

        {
            const float* __restrict__ qsrc = g_q + (b * TSEQ + qb * 64) * HDIM;
            #pragma unroll
            for (int p = 0; p < 4; p++) {
                const int row = lrow0 + p * 16;
                float4 q4 = *(const float4*)(qsrc + row * HDIM + lcol);
                q4.x *= scale; q4.y *= scale; q4.z *= scale; q4.w *= scale;
                *(float4*)(Qs + row * AT_STR + lcol) = q4;
                *(float4*)(Ks + row * AT_STR + lcol) =
                    *(const float4*)(kbase + row * HDIM + lcol);
                *(float4*)(Vs + row * AT_STR + lcol) =
                    *(const float4*)(vbase + row * HDIM + lcol);
            }
        }

        float m_i[4], l_i[4];
        #pragma unroll
        for (int ii = 0; ii < 4; ii++) { m_i[ii] = NEGBIG; l_i[ii] = 0.0f; }
        u64 o01[4] = {}, o23[4] = {};

        __syncthreads();

        for (int jt = 0; jt <= qb; jt++) {
            const int cur = jt & 1;
            float* __restrict__ Kc = Ks + cur * KV_BUF;
            float* __restrict__ Vc = Vs + cur * KV_BUF;

            float4 kpf[4], vpf[4];
            const bool pf = (jt < qb);
            if (pf) {
                const float* __restrict__ ksrc = kbase + (jt + 1) * 64 * HDIM;
                const float* __restrict__ vsrc = vbase + (jt + 1) * 64 * HDIM;
                #pragma unroll
                for (int p = 0; p < 4; p++) {
                    const int row = lrow0 + p * 16;
                    kpf[p] = *(const float4*)(ksrc + row * HDIM + lcol);
                    vpf[p] = *(const float4*)(vsrc + row * HDIM + lcol);
                }
            }

            u64 sp[4][4] = {};
            #pragma unroll
            for (int kk = 0; kk < 64; kk += 4) {
                ulonglong2 a2[4], b2[4];
                #pragma unroll
                for (int ii = 0; ii < 4; ii++)
                    a2[ii] = *(const ulonglong2*)(Qs + (ty + 16 * ii) * AT_STR + kk);
                #pragma unroll
                for (int jj = 0; jj < 4; jj++)
                    b2[jj] = *(const ulonglong2*)(Kc + (tx + 16 * jj) * AT_STR + kk);
                #pragma unroll
                for (int ii = 0; ii < 4; ii++)
                    #pragma unroll
                    for (int jj = 0; jj < 4; jj++) {
                        fma2(sp[ii][jj], a2[ii].x, b2[jj].x);
                        fma2(sp[ii][jj], a2[ii].y, b2[jj].y);
                    }
            }
            float s[4][4];
            #pragma unroll
            for (int ii = 0; ii < 4; ii++)
                #pragma unroll
                for (int jj = 0; jj < 4; jj++) {
                    float lo, hi;
                    upk2(lo, hi, sp[ii][jj]);
                    s[ii][jj] = lo + hi;
                }

            if (jt == qb) {
                #pragma unroll
                for (int ii = 0; ii < 4; ii++)
                    #pragma unroll
                    for (int jj = 0; jj < 4; jj++)
                        if ((tx + 16 * jj) > (ty + 16 * ii)) s[ii][jj] = NEGBIG;
            }

            #pragma unroll
            for (int ii = 0; ii < 4; ii++) {
                float tm = fmaxf(fmaxf(s[ii][0], s[ii][1]),
                                 fmaxf(s[ii][2], s[ii][3]));
                #pragma unroll
                for (int w = 1; w < 16; w <<= 1)
                    tm = fmaxf(tm, __shfl_xor_sync(0xffffffffu, tm, w));
                const float mnew = fmaxf(m_i[ii], tm);
                const float alpha = __expf(m_i[ii] - mnew);
                m_i[ii] = mnew;

                float p0 = __expf(s[ii][0] - mnew);
                float p1 = __expf(s[ii][1] - mnew);
                float p2 = __expf(s[ii][2] - mnew);
                float p3 = __expf(s[ii][3] - mnew);
                float rs = (p0 + p1) + (p2 + p3);
                #pragma unroll
                for (int w = 1; w < 16; w <<= 1)
                    rs += __shfl_xor_sync(0xffffffffu, rs, w);
                l_i[ii] = l_i[ii] * alpha + rs;

                const u64 ad = pk2(alpha, alpha);
                mul2(o01[ii], ad);
                mul2(o23[ii], ad);

                const int pc = ty * 4 + ii;
                St[(tx +  0) * AT_STR + pc] = p0;
                St[(tx + 16) * AT_STR + pc] = p1;
                St[(tx + 32) * AT_STR + pc] = p2;
                St[(tx + 48) * AT_STR + pc] = p3;
            }
            __syncthreads();

            #pragma unroll 8
            for (int j = 0; j < 64; j++) {
                const float4 pv = *(const float4*)(St + j * AT_STR + ty * 4);
                const ulonglong2 vv =
                    *(const ulonglong2*)(Vc + j * AT_STR + tx * 4);
                const float pa[4] = {pv.x, pv.y, pv.z, pv.w};
                #pragma unroll
                for (int ii = 0; ii < 4; ii++) {
                    const u64 pd = pk2(pa[ii], pa[ii]);
                    fma2(o01[ii], pd, vv.x);
                    fma2(o23[ii], pd, vv.y);
                }
            }

            if (pf) {
                float* __restrict__ Kn = Ks + (1 - cur) * KV_BUF;
                float* __restrict__ Vn = Vs + (1 - cur) * KV_BUF;
                #pragma unroll
                for (int p = 0; p < 4; p++) {
                    const int row = lrow0 + p * 16;
                    *(float4*)(Kn + row * AT_STR + lcol) = kpf[p];
                    *(float4*)(Vn + row * AT_STR + lcol) = vpf[p];
                }
            }
            __syncthreads();
        }

        #pragma unroll
        for (int ii = 0; ii < 4; ii++) {
            const int i     = ty + 16 * ii;
            const float inv = 1.0f / l_i[ii];
            float c0, c1, c2, c3;
            upk2(c0, c1, o01[ii]);
            upk2(c2, c3, o23[ii]);
            float4 ov;
            ov.x = c0 * inv; ov.y = c1 * inv;
            ov.z = c2 * inv; ov.w = c3 * inv;
            *(float4*)(out + (b * TSEQ + qb * 64 + i) * HDIM + tx * 4) = ov;
        }
    }
}

// ---------------------------------------------------------------------------
// kernel_launch — inputs (metadata order): x, mask(int32, unused), Wk, Wq, Wv
// ---------------------------------------------------------------------------
extern "C" void kernel_launch(void* const* d_in, const int* in_sizes, int n_in,
                              void* d_out, int out_size)
{
    const float* x  = (const float*)d_in[0];
    const float* Wk = (const float*)d_in[2];
    const float* Wq = (const float*)d_in[3];
    const float* Wv = (const float*)d_in[4];
    float* out = (float*)d_out;

    cudaFuncSetAttribute(attn_kernel,
                         cudaFuncAttributeMaxDynamicSharedMemorySize,
                         ATTN_SMEM_BYTES);
    cudaFuncSetAttribute(proj_mma_kernel,
                         cudaFuncAttributeMaxDynamicSharedMemorySize,
                         PM_SMEM);

    // resolve device-global buffer addresses (host-side, capture-safe)
    __nv_bfloat16 *xh, *xl, *wh, *wl;
    cudaGetSymbolAddress((void**)&xh, g_xh);
    cudaGetSymbolAddress((void**)&xl, g_xl);
    cudaGetSymbolAddress((void**)&wh, g_wh);
    cudaGetSymbolAddress((void**)&wl, g_wl);

    // bf16 two-term splits
    const int nx = MROWS * CDIM;          // 16M
    const int nw = HDIM * CDIM;           // 64K
    cvt_split_kernel<<<nx / (256 * 4), 256>>>(x,  xh, xl, nx);
    cvt_split_kernel<<<nw / (256 * 4), 256>>>(Wq, wh + 0 * nw, wl + 0 * nw, nw);
    cvt_split_kernel<<<nw / (256 * 4), 256>>>(Wk, wh + 1 * nw, wl + 1 * nw, nw);
    cvt_split_kernel<<<nw / (256 * 4), 256>>>(Wv, wh + 2 * nw, wl + 2 * nw, nw);

    // projection on tensor cores (legacy mma.sync path)
    dim3 pgrid(MROWS / 128, 3);
    proj_mma_kernel<<<pgrid, 256, PM_SMEM>>>();

    // attention (R8, best measured)
    dim3 agrid(32, NB);
    attn_kernel<<<agrid, 256, ATTN_SMEM_BYTES>>>(out);
}

// round 13
// speedup vs baseline: 2.4204x; 1.7408x over previous
#include <cuda_runtime.h>
#include <cuda_bf16.h>
#include <cstdint>

// Problem constants
#define NB    4
#define TSEQ  4096
#define CDIM  1024
#define HDIM  64
#define MROWS (NB * TSEQ)   // 16384

__device__ __forceinline__ uint32_t smem_to_u32(const void* p) {
    uint32_t a;
    asm("{ .reg .u64 t; cvta.to.shared.u64 t, %1; cvt.u32.u64 %0, t; }"
        : "=r"(a) : "l"(p));
    return a;
}
#define SMEM_SWIZZLE_128B(off) ((off) ^ (((off) >> 3) & 0x70))

// ---- legacy tensor-core path (compute_103-legal): ldmatrix + mma.sync ----
__device__ __forceinline__ void ldsm_x4(uint32_t& r0, uint32_t& r1,
                                        uint32_t& r2, uint32_t& r3,
                                        uint32_t addr) {
    asm volatile("ldmatrix.sync.aligned.m8n8.x4.shared.b16 {%0,%1,%2,%3}, [%4];"
                 : "=r"(r0), "=r"(r1), "=r"(r2), "=r"(r3) : "r"(addr));
}
__device__ __forceinline__ void mma_bf16(float* d, const uint32_t* a,
                                         const uint32_t* b) {
    asm volatile(
        "mma.sync.aligned.m16n8k16.row.col.f32.bf16.bf16.f32 "
        "{%0,%1,%2,%3}, {%4,%5,%6,%7}, {%8,%9}, {%0,%1,%2,%3};"
        : "+f"(d[0]), "+f"(d[1]), "+f"(d[2]), "+f"(d[3])
        : "r"(a[0]), "r"(a[1]), "r"(a[2]), "r"(a[3]), "r"(b[0]), "r"(b[1]));
}
// pack two fp32 -> bf16x2 (lo, hi) using the documented intrinsic layout (x = low)
__device__ __forceinline__ uint32_t pack_bf2(float lo, float hi) {
    __nv_bfloat162 v = __floats2bfloat162_rn(lo, hi);
    return *reinterpret_cast<uint32_t*>(&v);
}

// Scratch (device globals per alloc rules)
__device__ __nv_bfloat16 g_xh[MROWS * CDIM];        // 32 MB
__device__ __nv_bfloat16 g_xl[MROWS * CDIM];        // 32 MB
__device__ __nv_bfloat16 g_wh[3 * HDIM * CDIM];
__device__ __nv_bfloat16 g_wl[3 * HDIM * CDIM];
__device__ __nv_bfloat16 g_qh[MROWS * HDIM];        // Q pre-scaled by 0.125
__device__ __nv_bfloat16 g_ql[MROWS * HDIM];
__device__ __nv_bfloat16 g_kh[MROWS * HDIM];
__device__ __nv_bfloat16 g_kl[MROWS * HDIM];
__device__ __nv_bfloat16 g_vth[HDIM * MROWS];       // V transposed [h][m]
__device__ __nv_bfloat16 g_vtl[HDIM * MROWS];

// ---------------------------------------------------------------------------
// fp32 -> bf16 two-term split of inputs
// ---------------------------------------------------------------------------
__global__ __launch_bounds__(256) void cvt_split_kernel(
    const float* __restrict__ src,
    __nv_bfloat16* __restrict__ dhi,
    __nv_bfloat16* __restrict__ dlo, int n)
{
    const int i = (blockIdx.x * 256 + threadIdx.x) * 4;
    if (i >= n) return;
    const float4 v = *(const float4*)(src + i);
    const float vv[4] = {v.x, v.y, v.z, v.w};
    __nv_bfloat16 h[4], l[4];
    #pragma unroll
    for (int k = 0; k < 4; k++) {
        h[k] = __float2bfloat16(vv[k]);
        l[k] = __float2bfloat16(vv[k] - __bfloat162float(h[k]));
    }
    *(uint2*)(dhi + i) = *(uint2*)h;
    *(uint2*)(dlo + i) = *(uint2*)l;
}

// ---------------------------------------------------------------------------
// Projection via mma.sync bf16-split. Emits bf16-split q (pre-scaled), k
// row-major; v TRANSPOSED [h][m] — exactly what the attention kernel consumes.
// BM=128, BN=64, BK=64; 256 thr = 8 warps (4Mx2N). grid (MROWS/128, 3).
// ---------------------------------------------------------------------------
#define PM_AH   0
#define PM_AL   16384
#define PM_BH   32768
#define PM_BL   40960
#define PM_SMEM 49152

__global__ __launch_bounds__(256) void proj_mma_kernel()
{
    extern __shared__ char smem[];
    const uint32_t sb = smem_to_u32(smem);
    const int t   = threadIdx.x;
    const int wid = t >> 5;
    const int lid = t & 31;
    const int m0  = blockIdx.x * 128;
    const int ws  = blockIdx.y;

    const __nv_bfloat16* __restrict__ Wh = g_wh + ws * HDIM * CDIM;
    const __nv_bfloat16* __restrict__ Wl = g_wl + ws * HDIM * CDIM;

    const int warp_m = (wid >> 1) * 32;
    const int warp_n = (wid & 1) * 32;
    const int g  = lid >> 3;
    const int r  = lid & 7;

    float d[2][4][4] = {};

    for (int kb = 0; kb < CDIM; kb += 64) {
        #pragma unroll
        for (int p = 0; p < 4; p++) {
            const int u   = t + p * 256;
            const int row = u >> 3;
            const int cu  = u & 7;
            const uint32_t so = SMEM_SWIZZLE_128B((uint32_t)(row * 128 + cu * 16));
            const long gi = (long)(m0 + row) * CDIM + kb + cu * 8;
            *(uint4*)(smem + PM_AH + so) = *(const uint4*)(g_xh + gi);
            *(uint4*)(smem + PM_AL + so) = *(const uint4*)(g_xl + gi);
        }
        #pragma unroll
        for (int p = 0; p < 2; p++) {
            const int u   = t + p * 256;
            const int row = u >> 3;
            const int cu  = u & 7;
            const uint32_t so = SMEM_SWIZZLE_128B((uint32_t)(row * 128 + cu * 16));
            const int gi = row * CDIM + kb + cu * 8;
            *(uint4*)(smem + PM_BH + so) = *(const uint4*)(Wh + gi);
            *(uint4*)(smem + PM_BL + so) = *(const uint4*)(Wl + gi);
        }
        __syncthreads();

        #pragma unroll
        for (int ks = 0; ks < 4; ks++) {
            const int k0 = ks * 16;
            uint32_t ah[2][4], al[2][4];
            #pragma unroll
            for (int mt = 0; mt < 2; mt++) {
                const int arow = warp_m + mt * 16 + r + (g & 1) * 8;
                const int acol = k0 + (g >> 1) * 8;
                const uint32_t so =
                    SMEM_SWIZZLE_128B((uint32_t)(arow * 128 + acol * 2));
                ldsm_x4(ah[mt][0], ah[mt][1], ah[mt][2], ah[mt][3],
                        sb + PM_AH + so);
                ldsm_x4(al[mt][0], al[mt][1], al[mt][2], al[mt][3],
                        sb + PM_AL + so);
            }
            uint32_t bh[4][2], bl[4][2];
            #pragma unroll
            for (int np = 0; np < 2; np++) {
                const int brow = warp_n + np * 16 + r + (g >> 1) * 8;
                const int bcol = k0 + (g & 1) * 8;
                const uint32_t so =
                    SMEM_SWIZZLE_128B((uint32_t)(brow * 128 + bcol * 2));
                uint32_t r0, r1, r2, r3;
                ldsm_x4(r0, r1, r2, r3, sb + PM_BH + so);
                bh[np * 2 + 0][0] = r0; bh[np * 2 + 0][1] = r1;
                bh[np * 2 + 1][0] = r2; bh[np * 2 + 1][1] = r3;
                ldsm_x4(r0, r1, r2, r3, sb + PM_BL + so);
                bl[np * 2 + 0][0] = r0; bl[np * 2 + 0][1] = r1;
                bl[np * 2 + 1][0] = r2; bl[np * 2 + 1][1] = r3;
            }
            #pragma unroll
            for (int mt = 0; mt < 2; mt++)
                #pragma unroll
                for (int nt = 0; nt < 4; nt++) {
                    mma_bf16(d[mt][nt], ah[mt], bh[nt]);
                    mma_bf16(d[mt][nt], ah[mt], bl[nt]);
                    mma_bf16(d[mt][nt], al[mt], bh[nt]);
                }
        }
        __syncthreads();
    }

    // epilogue: split to bf16 hi/lo; Q pre-scaled; V transposed
    const int qrow = lid >> 2;
    const int qcol = (lid & 3) * 2;
    const float sc = (ws == 0) ? 0.125f : 1.0f;

    if (ws < 2) {
        __nv_bfloat16* __restrict__ dh = (ws == 0) ? g_qh : g_kh;
        __nv_bfloat16* __restrict__ dl = (ws == 0) ? g_ql : g_kl;
        #pragma unroll
        for (int mt = 0; mt < 2; mt++)
            #pragma unroll
            for (int nt = 0; nt < 4; nt++) {
                const int col = warp_n + nt * 8 + qcol;
                #pragma unroll
                for (int e = 0; e < 2; e++) {   // e=0: rows qrow; e=1: +8
                    const long rowg = m0 + warp_m + mt * 16 + qrow + e * 8;
                    const float v0 = d[mt][nt][e * 2 + 0] * sc;
                    const float v1 = d[mt][nt][e * 2 + 1] * sc;
                    const __nv_bfloat162 hh = __floats2bfloat162_rn(v0, v1);
                    const float r0 = v0 - __low2float(hh);
                    const float r1 = v1 - __high2float(hh);
                    const __nv_bfloat162 ll = __floats2bfloat162_rn(r0, r1);
                    *(uint32_t*)(dh + rowg * HDIM + col) =
                        *(const uint32_t*)&hh;
                    *(uint32_t*)(dl + rowg * HDIM + col) =
                        *(const uint32_t*)&ll;
                }
            }
    } else {
        #pragma unroll
        for (int mt = 0; mt < 2; mt++)
            #pragma unroll
            for (int nt = 0; nt < 4; nt++) {
                #pragma unroll
                for (int e = 0; e < 4; e++) {
                    const long rowg = m0 + warp_m + mt * 16 + qrow + (e >> 1) * 8;
                    const int  colg = warp_n + nt * 8 + qcol + (e & 1);
                    const float v = d[mt][nt][(e >> 1) * 2 + (e & 1)];
                    const __nv_bfloat16 h = __float2bfloat16(v);
                    g_vth[(long)colg * MROWS + rowg] = h;
                    g_vtl[(long)colg * MROWS + rowg] =
                        __float2bfloat16(v - __bfloat162float(h));
                }
            }
    }
}

// ---------------------------------------------------------------------------
// Flash attention on tensor cores (bf16-split, fp32 accum).
// grid (32, 4), 256 thr = 8 warps. CTA does q-tile pair (63-bx, bx): 65 iters.
// Warp w: rows mb=w>>1 (m16), S cols nb=w&1 (n32). P reused in-register as
// PV A-fragments (D-frag == A-frag ownership). Per-warp partial O/l over its
// j-slice; merged once in epilogue. 2 barriers/iter. K/V double-buffered.
// ---------------------------------------------------------------------------
#define AQH   0
#define AQL   8192
#define AKH   16384
#define AKL   24576
#define AVH   32768
#define AVL   40960
#define ASET  32768          // byte stride between buffer set 0 and 1
#define APMX  81920          // 8 warps x 16 floats
#define ALEX  82432          // 64 floats
#define AOEX  82688          // 64x64 fp32
#define ATT_SMEM (82688 + 16384)   // 99072 bytes

__global__ __launch_bounds__(256) void attn_kernel(float* __restrict__ out)
{
    extern __shared__ char smc[];
    const uint32_t sb = smem_to_u32(smc);
    float* pmx = (float*)(smc + APMX);
    float* lex = (float*)(smc + ALEX);
    float* oex = (float*)(smc + AOEX);

    const int t   = threadIdx.x;
    const int lid = t & 31;
    const int wid = t >> 5;
    const int mb  = wid >> 1;           // m16 block 0..3
    const int nb  = wid & 1;            // n32 block 0..1
    const int g   = lid >> 3;
    const int r   = lid & 7;
    const int bx  = blockIdx.x;
    const int b   = blockIdx.y;

    // cooperative tile-load map: u = t + p*256 -> row=u>>3, col-u4 = u&7
    const int lrow[2] = { t >> 3, (t + 256) >> 3 };
    const int lcu  = t & 7;
    const uint32_t lso[2] = {
        SMEM_SWIZZLE_128B((uint32_t)(lrow[0] * 128 + lcu * 16)),
        SMEM_SWIZZLE_128B((uint32_t)(lrow[1] * 128 + lcu * 16)) };

    // fragment row/col ownership
    const int i0 = mb * 16 + (lid >> 2);          // row of c0/c1
    const int jb = nb * 32 + (lid & 3) * 2;       // col base of c0

    const long bT = (long)b * TSEQ;

    #pragma unroll 1
    for (int half = 0; half < 2; half++) {
        const int qb = (half == 0) ? (63 - bx) : bx;

        // ---- prologue: Q tiles + K/V tile 0 into set 0 ----
        #pragma unroll
        for (int p = 0; p < 2; p++) {
            const long qg = (bT + qb * 64 + lrow[p]) * HDIM + lcu * 8;
            *(uint4*)(smc + AQH + lso[p]) = *(const uint4*)(g_qh + qg);
            *(uint4*)(smc + AQL + lso[p]) = *(const uint4*)(g_ql + qg);
            const long kg = (bT + lrow[p]) * HDIM + lcu * 8;
            *(uint4*)(smc + AKH + lso[p]) = *(const uint4*)(g_kh + kg);
            *(uint4*)(smc + AKL + lso[p]) = *(const uint4*)(g_kl + kg);
            const long vg = (long)lrow[p] * MROWS + bT + lcu * 8;
            *(uint4*)(smc + AVH + lso[p]) = *(const uint4*)(g_vth + vg);
            *(uint4*)(smc + AVL + lso[p]) = *(const uint4*)(g_vtl + vg);
        }
        __syncthreads();

        // ---- hoist Q A-fragments (fixed per half) ----
        uint32_t qah[4][4], qal[4][4];
        #pragma unroll
        for (int kst = 0; kst < 4; kst++) {
            const int arow = mb * 16 + r + (g & 1) * 8;
            const int acol = kst * 16 + (g >> 1) * 8;
            const uint32_t so =
                SMEM_SWIZZLE_128B((uint32_t)(arow * 128 + acol * 2));
            ldsm_x4(qah[kst][0], qah[kst][1], qah[kst][2], qah[kst][3],
                    sb + AQH + so);
            ldsm_x4(qal[kst][0], qal[kst][1], qal[kst][2], qal[kst][3],
                    sb + AQL + so);
        }

        float o[8][4] = {};          // O partial: m16 x n64 (8 n8 tiles)
        float l0 = 0.f, l1 = 0.f;    // partial row sums (rows i0, i0+8)
        float m0r = -1e30f, m1r = -1e30f;

        for (int jt = 0; jt <= qb; jt++) {
            const uint32_t cs = (uint32_t)(jt & 1) * ASET;
            const uint32_t ns = (uint32_t)((jt & 1) ^ 1) * ASET;
            const bool pf = (jt < qb);

            // ---- prefetch next K/V tile into registers ----
            uint4 pk[2], pkl[2], pv[2], pvl[2];
            if (pf) {
                #pragma unroll
                for (int p = 0; p < 2; p++) {
                    const long kg = (bT + (jt + 1) * 64 + lrow[p]) * HDIM + lcu * 8;
                    pk [p] = *(const uint4*)(g_kh + kg);
                    pkl[p] = *(const uint4*)(g_kl + kg);
                    const long vg = (long)lrow[p] * MROWS + bT + (jt + 1) * 64 + lcu * 8;
                    pv [p] = *(const uint4*)(g_vth + vg);
                    pvl[p] = *(const uint4*)(g_vtl + vg);
                }
            }

            // ---- S = Q @ K^T (3 split products) ----
            float s[4][4] = {};
            #pragma unroll
            for (int kst = 0; kst < 4; kst++) {
                uint32_t bh[4][2], bl[4][2];
                #pragma unroll
                for (int np = 0; np < 2; np++) {
                    const int brow = nb * 32 + np * 16 + r + (g >> 1) * 8;
                    const int bcol = kst * 16 + (g & 1) * 8;
                    const uint32_t so =
                        SMEM_SWIZZLE_128B((uint32_t)(brow * 128 + bcol * 2));
                    uint32_t r0, r1, r2, r3;
                    ldsm_x4(r0, r1, r2, r3, sb + AKH + cs + so);
                    bh[np * 2 + 0][0] = r0; bh[np * 2 + 0][1] = r1;
                    bh[np * 2 + 1][0] = r2; bh[np * 2 + 1][1] = r3;
                    ldsm_x4(r0, r1, r2, r3, sb + AKL + cs + so);
                    bl[np * 2 + 0][0] = r0; bl[np * 2 + 0][1] = r1;
                    bl[np * 2 + 1][0] = r2; bl[np * 2 + 1][1] = r3;
                }
                #pragma unroll
                for (int nt = 0; nt < 4; nt++) {
                    mma_bf16(s[nt], qah[kst], bh[nt]);
                    mma_bf16(s[nt], qah[kst], bl[nt]);
                    mma_bf16(s[nt], qal[kst], bh[nt]);
                }
            }

            // ---- causal mask on diagonal tile ----
            if (jt == qb) {
                #pragma unroll
                for (int nt = 0; nt < 4; nt++) {
                    const int jj = jb + nt * 8;
                    if (jj     > i0)     s[nt][0] = -1e30f;
                    if (jj + 1 > i0)     s[nt][1] = -1e30f;
                    if (jj     > i0 + 8) s[nt][2] = -1e30f;
                    if (jj + 1 > i0 + 8) s[nt][3] = -1e30f;
                }
            }

            // ---- row max: lane partial -> 4-lane shfl -> cross-warp via smem
            float mx0 = fmaxf(fmaxf(s[0][0], s[0][1]), fmaxf(s[1][0], s[1][1]));
            mx0 = fmaxf(mx0, fmaxf(fmaxf(s[2][0], s[2][1]), fmaxf(s[3][0], s[3][1])));
            float mx1 = fmaxf(fmaxf(s[0][2], s[0][3]), fmaxf(s[1][2], s[1][3]));
            mx1 = fmaxf(mx1, fmaxf(fmaxf(s[2][2], s[2][3]), fmaxf(s[3][2], s[3][3])));
            mx0 = fmaxf(mx0, __shfl_xor_sync(0xffffffffu, mx0, 1));
            mx0 = fmaxf(mx0, __shfl_xor_sync(0xffffffffu, mx0, 2));
            mx1 = fmaxf(mx1, __shfl_xor_sync(0xffffffffu, mx1, 1));
            mx1 = fmaxf(mx1, __shfl_xor_sync(0xffffffffu, mx1, 2));
            if ((lid & 3) == 0) {
                pmx[wid * 16 + (lid >> 2)]     = mx0;
                pmx[wid * 16 + 8 + (lid >> 2)] = mx1;
            }
            __syncthreads();                                  // barrier 1
            const float om0 = pmx[(wid ^ 1) * 16 + (lid >> 2)];
            const float om1 = pmx[(wid ^ 1) * 16 + 8 + (lid >> 2)];
            const float mn0 = fmaxf(m0r, fmaxf(mx0, om0));
            const float mn1 = fmaxf(m1r, fmaxf(mx1, om1));
            const float al0 = __expf(m0r - mn0);
            const float al1 = __expf(m1r - mn1);
            m0r = mn0; m1r = mn1;

            // ---- P = exp(S-m); partial row sums; O rescale ----
            float rs0 = 0.f, rs1 = 0.f;
            #pragma unroll
            for (int nt = 0; nt < 4; nt++) {
                s[nt][0] = __expf(s[nt][0] - mn0);
                s[nt][1] = __expf(s[nt][1] - mn0);
                s[nt][2] = __expf(s[nt][2] - mn1);
                s[nt][3] = __expf(s[nt][3] - mn1);
                rs0 += s[nt][0] + s[nt][1];
                rs1 += s[nt][2] + s[nt][3];
            }
            rs0 += __shfl_xor_sync(0xffffffffu, rs0, 1);
            rs0 += __shfl_xor_sync(0xffffffffu, rs0, 2);
            rs1 += __shfl_xor_sync(0xffffffffu, rs1, 1);
            rs1 += __shfl_xor_sync(0xffffffffu, rs1, 2);
            l0 = l0 * al0 + rs0;
            l1 = l1 * al1 + rs1;
            #pragma unroll
            for (int nt = 0; nt < 8; nt++) {
                o[nt][0] *= al0; o[nt][1] *= al0;
                o[nt][2] *= al1; o[nt][3] *= al1;
            }

            // ---- P fragments (in-register D->A reuse), hi/lo split ----
            uint32_t pah[2][4], pal[2][4];
            #pragma unroll
            for (int h2 = 0; h2 < 2; h2++) {
                const int n0 = h2 * 2, n1 = h2 * 2 + 1;
                const float pv4[4][2] = {
                    { s[n0][0], s[n0][1] }, { s[n0][2], s[n0][3] },
                    { s[n1][0], s[n1][1] }, { s[n1][2], s[n1][3] } };
                #pragma unroll
                for (int q = 0; q < 4; q++) {
                    const __nv_bfloat162 hh =
                        __floats2bfloat162_rn(pv4[q][0], pv4[q][1]);
                    const float r0f = pv4[q][0] - __low2float(hh);
                    const float r1f = pv4[q][1] - __high2float(hh);
                    const __nv_bfloat162 ll = __floats2bfloat162_rn(r0f, r1f);
                    pah[h2][q] = *(const uint32_t*)&hh;
                    pal[h2][q] = *(const uint32_t*)&ll;
                }
            }

            // ---- O += P @ V (warp's j-slice; 3 split products) ----
            #pragma unroll
            for (int kst = 0; kst < 2; kst++) {
                uint32_t vbh[8][2], vbl[8][2];
                #pragma unroll
                for (int np = 0; np < 4; np++) {
                    const int brow = np * 16 + r + (g >> 1) * 8;
                    const int bcol = nb * 32 + kst * 16 + (g & 1) * 8;
                    const uint32_t so =
                        SMEM_SWIZZLE_128B((uint32_t)(brow * 128 + bcol * 2));
                    uint32_t r0, r1, r2, r3;
                    ldsm_x4(r0, r1, r2, r3, sb + AVH + cs + so);
                    vbh[np * 2 + 0][0] = r0; vbh[np * 2 + 0][1] = r1;
                    vbh[np * 2 + 1][0] = r2; vbh[np * 2 + 1][1] = r3;
                    ldsm_x4(r0, r1, r2, r3, sb + AVL + cs + so);
                    vbl[np * 2 + 0][0] = r0; vbl[np * 2 + 0][1] = r1;
                    vbl[np * 2 + 1][0] = r2; vbl[np * 2 + 1][1] = r3;
                }
                #pragma unroll
                for (int nt = 0; nt < 8; nt++) {
                    mma_bf16(o[nt], pah[kst], vbh[nt]);
                    mma_bf16(o[nt], pah[kst], vbl[nt]);
                    mma_bf16(o[nt], pal[kst], vbh[nt]);
                }
            }

            // ---- stage prefetched tiles into alternate set ----
            if (pf) {
                #pragma unroll
                for (int p = 0; p < 2; p++) {
                    *(uint4*)(smc + AKH + ns + lso[p]) = pk [p];
                    *(uint4*)(smc + AKL + ns + lso[p]) = pkl[p];
                    *(uint4*)(smc + AVH + ns + lso[p]) = pv [p];
                    *(uint4*)(smc + AVL + ns + lso[p]) = pvl[p];
                }
            }
            __syncthreads();                                  // barrier 2
        }

        // ---- epilogue: merge partner-warp partials, normalize, store ----
        if (nb == 1) {
            #pragma unroll
            for (int nt = 0; nt < 8; nt++) {
                const int col = nt * 8 + (lid & 3) * 2;
                *(float2*)(oex + i0 * 64 + col)       = make_float2(o[nt][0], o[nt][1]);
                *(float2*)(oex + (i0 + 8) * 64 + col) = make_float2(o[nt][2], o[nt][3]);
            }
            if ((lid & 3) == 0) { lex[i0] = l0; lex[i0 + 8] = l1; }
        }
        __syncthreads();
        if (nb == 0) {
            const float inv0 = 1.0f / (l0 + lex[i0]);
            const float inv1 = 1.0f / (l1 + lex[i0 + 8]);
            #pragma unroll
            for (int nt = 0; nt < 8; nt++) {
                const int col = nt * 8 + (lid & 3) * 2;
                const float2 p0 = *(const float2*)(oex + i0 * 64 + col);
                const float2 p1 = *(const float2*)(oex + (i0 + 8) * 64 + col);
                *(float2*)(out + (bT + qb * 64 + i0) * HDIM + col) =
                    make_float2((o[nt][0] + p0.x) * inv0, (o[nt][1] + p0.y) * inv0);
                *(float2*)(out + (bT + qb * 64 + i0 + 8) * HDIM + col) =
                    make_float2((o[nt][2] + p1.x) * inv1, (o[nt][3] + p1.y) * inv1);
            }
        }
        __syncthreads();
    }
}

// ---------------------------------------------------------------------------
// kernel_launch — inputs (metadata order): x, mask(int32, unused), Wk, Wq, Wv
// ---------------------------------------------------------------------------
extern "C" void kernel_launch(void* const* d_in, const int* in_sizes, int n_in,
                              void* d_out, int out_size)
{
    const float* x  = (const float*)d_in[0];
    const float* Wk = (const float*)d_in[2];
    const float* Wq = (const float*)d_in[3];
    const float* Wv = (const float*)d_in[4];
    float* out = (float*)d_out;

    cudaFuncSetAttribute(proj_mma_kernel,
                         cudaFuncAttributeMaxDynamicSharedMemorySize, PM_SMEM);
    cudaFuncSetAttribute(attn_kernel,
                         cudaFuncAttributeMaxDynamicSharedMemorySize, ATT_SMEM);

    __nv_bfloat16 *xh, *xl, *wh, *wl;
    cudaGetSymbolAddress((void**)&xh, g_xh);
    cudaGetSymbolAddress((void**)&xl, g_xl);
    cudaGetSymbolAddress((void**)&wh, g_wh);
    cudaGetSymbolAddress((void**)&wl, g_wl);

    const int nx = MROWS * CDIM;
    const int nw = HDIM * CDIM;
    cvt_split_kernel<<<nx / (256 * 4), 256>>>(x,  xh, xl, nx);
    cvt_split_kernel<<<nw / (256 * 4), 256>>>(Wq, wh + 0 * nw, wl + 0 * nw, nw);
    cvt_split_kernel<<<nw / (256 * 4), 256>>>(Wk, wh + 1 * nw, wl + 1 * nw, nw);
    cvt_split_kernel<<<nw / (256 * 4), 256>>>(Wv, wh + 2 * nw, wl + 2 * nw, nw);

    dim3 pgrid(MROWS / 128, 3);
    proj_mma_kernel<<<pgrid, 256, PM_SMEM>>>();

    dim3 agrid(32, NB);
    attn_kernel<<<agrid, 256, ATT_SMEM>>>(out);
}